// round 3
// baseline (speedup 1.0000x reference)
#include <cuda_runtime.h>

#define N_NODES 65536
#define C 128
#define BGR 128
#define NPG 512
#define KSEL 256
#define E_MAX 1114112

// ---------------- device scratch (static, 16B-aligned for float4 access) ----------------
__device__ __align__(16) float g_h[N_NODES * C];     // relu(x@W1+b1)
__device__ __align__(16) float g_xc[N_NODES * C];    // cluster reps
__device__ __align__(16) float g_v[C];               // Wp @ Wa[:128]
__device__ __align__(16) float g_S[BGR * C];         // per-graph weighted sums
__device__ float g_hdot[N_NODES];      // h . Wa[128:256]
__device__ float g_a[N_NODES];         // xc.Wl1 + bl1
__device__ float g_fitp[N_NODES];      // xc.Wl3 + bl3 - deg * (xc.Wl2)
__device__ float g_fit[N_NODES];
__device__ int   g_deg[N_NODES];
__device__ int   g_cur[N_NODES];
__device__ int   g_off[N_NODES + 1];
__device__ int   g_csr[E_MAX];
__device__ float g_c;                  // bp.Wa[:128] + ba

__device__ __forceinline__ float wsum(float v) {
    #pragma unroll
    for (int o = 16; o > 0; o >>= 1) v += __shfl_xor_sync(0xffffffffu, v, o);
    return v;
}
__device__ __forceinline__ float wmax(float v) {
    #pragma unroll
    for (int o = 16; o > 0; o >>= 1) v = fmaxf(v, __shfl_xor_sync(0xffffffffu, v, o));
    return v;
}

// ---------------- init ----------------
__global__ void k_zero() {
    int i = blockIdx.x * blockDim.x + threadIdx.x;
    if (i < N_NODES) { g_deg[i] = 0; g_cur[i] = 0; }
}

// v[k] = sum_j Wp[k,j]*Wa[j];  c = bp.Wa[:128] + ba
__global__ void k_prep(const float* __restrict__ Wp, const float* __restrict__ bp,
                       const float* __restrict__ Wa, const float* __restrict__ ba) {
    int t = threadIdx.x;  // 128 threads
    float s = 0.f;
    #pragma unroll 4
    for (int j = 0; j < C; j++) s += Wp[t * C + j] * Wa[j];
    g_v[t] = s;
    __shared__ float red[C];
    red[t] = bp[t] * Wa[t];
    __syncthreads();
    for (int o = 64; o > 0; o >>= 1) {
        if (t < o) red[t] += red[t + o];
        __syncthreads();
    }
    if (t == 0) g_c = red[0] + ba[0];
}

// ---------------- h = relu(x @ W1 + b1) ----------------
__global__ void k_gemm_relu(const float* __restrict__ X, const float* __restrict__ W,
                            const float* __restrict__ bias) {
    __shared__ float Xs[16][128];  // [k][row]
    __shared__ float Ws[16][128];  // [k][col]
    int tid = threadIdx.x;
    int tx = tid & 15, ty = tid >> 4;
    int row0 = blockIdx.x * 128;
    float acc[8][8];
    #pragma unroll
    for (int j = 0; j < 8; j++)
        #pragma unroll
        for (int i = 0; i < 8; i++) acc[j][i] = 0.f;

    for (int k0 = 0; k0 < C; k0 += 16) {
        #pragma unroll
        for (int u = 0; u < 2; u++) {
            int f = tid * 2 + u;
            int r = f >> 2, c4 = (f & 3) * 4;
            float4 xv = *(const float4*)&X[(size_t)(row0 + r) * C + k0 + c4];
            Xs[c4 + 0][r] = xv.x; Xs[c4 + 1][r] = xv.y;
            Xs[c4 + 2][r] = xv.z; Xs[c4 + 3][r] = xv.w;
            int rw = f >> 5, cw = (f & 31) * 4;
            // scalar loads for W (robust to any base alignment)
            Ws[rw][cw + 0] = W[(size_t)(k0 + rw) * C + cw + 0];
            Ws[rw][cw + 1] = W[(size_t)(k0 + rw) * C + cw + 1];
            Ws[rw][cw + 2] = W[(size_t)(k0 + rw) * C + cw + 2];
            Ws[rw][cw + 3] = W[(size_t)(k0 + rw) * C + cw + 3];
        }
        __syncthreads();
        #pragma unroll
        for (int kk = 0; kk < 16; kk++) {
            float a[8], b[8];
            #pragma unroll
            for (int j = 0; j < 8; j++) a[j] = Xs[kk][ty * 8 + j];
            #pragma unroll
            for (int i = 0; i < 8; i++) b[i] = Ws[kk][tx + 16 * i];
            #pragma unroll
            for (int j = 0; j < 8; j++)
                #pragma unroll
                for (int i = 0; i < 8; i++) acc[j][i] = fmaf(a[j], b[i], acc[j][i]);
        }
        __syncthreads();
    }
    #pragma unroll
    for (int j = 0; j < 8; j++) {
        int row = row0 + ty * 8 + j;
        #pragma unroll
        for (int i = 0; i < 8; i++) {
            int col = tx + 16 * i;
            float r = acc[j][i] + bias[col];
            g_h[(size_t)row * C + col] = r > 0.f ? r : 0.f;
        }
    }
}

// hdot[i] = h[i] . Wa[128:256]   (warp per node; scalar weight loads)
__global__ void k_hdot(const float* __restrict__ Wa) {
    int w = (blockIdx.x * blockDim.x + threadIdx.x) >> 5;
    int lane = threadIdx.x & 31;
    if (w >= N_NODES) return;
    float4 hv = ((const float4*)g_h)[(size_t)w * 32 + lane];
    const float* wp = Wa + C + lane * 4;
    float d = wsum(hv.x * wp[0] + hv.y * wp[1] + hv.z * wp[2] + hv.w * wp[3]);
    if (lane == 0) g_hdot[w] = d;
}

// ---------------- CSR build (edge_index is int32!) ----------------
__global__ void k_hist(const int* __restrict__ ei, int E) {
    int e = blockIdx.x * blockDim.x + threadIdx.x;
    if (e < E) atomicAdd(&g_deg[ei[E + e]], 1);
}

__global__ void k_scan() {
    __shared__ int sums[1024];
    int t = threadIdx.x;
    int base = t * 64;
    int s = 0;
    #pragma unroll 8
    for (int i = 0; i < 64; i++) s += g_deg[base + i];
    sums[t] = s;
    __syncthreads();
    for (int d = 1; d < 1024; d <<= 1) {
        int v = (t >= d) ? sums[t - d] : 0;
        __syncthreads();
        sums[t] += v;
        __syncthreads();
    }
    int run = (t == 0) ? 0 : sums[t - 1];
    for (int i = 0; i < 64; i++) { g_off[base + i] = run; run += g_deg[base + i]; }
    if (t == 1023) g_off[N_NODES] = run;
}

__global__ void k_scatter(const int* __restrict__ ei, int E) {
    int e = blockIdx.x * blockDim.x + threadIdx.x;
    if (e >= E) return;
    int dst = ei[E + e];
    int src = ei[e];
    int p = g_off[dst] + atomicAdd(&g_cur[dst], 1);
    g_csr[p] = src;
}

// ---------------- ASAP attention: x_q max, softmax, xc  (warp per node) ----------------
__global__ void k_atten() {
    int w = (blockIdx.x * blockDim.x + threadIdx.x) >> 5;
    int lane = threadIdx.x & 31;
    if (w >= N_NODES) return;
    int s0 = g_off[w], s1 = g_off[w + 1];
    const float4* H4 = (const float4*)g_h;

    // pass 1: vector max over in-neighbors (h >= 0 so init 0 is safe)
    float4 m = make_float4(0.f, 0.f, 0.f, 0.f);
    for (int e = s0; e < s1; e++) {
        int s = g_csr[e];
        float4 hv = H4[(size_t)s * 32 + lane];
        m.x = fmaxf(m.x, hv.x); m.y = fmaxf(m.y, hv.y);
        m.z = fmaxf(m.z, hv.z); m.w = fmaxf(m.w, hv.w);
    }
    float4 vv = ((const float4*)g_v)[lane];
    float qd = wsum(m.x * vv.x + m.y * vv.y + m.z * vv.z + m.w * vv.w) + g_c;

    // pass 2: score max (lane-strided, scalars only)
    float smax = -3.0e38f;
    for (int e = s0 + lane; e < s1; e += 32) {
        float sc = qd + g_hdot[g_csr[e]];
        sc = sc > 0.f ? sc : 0.2f * sc;
        smax = fmaxf(smax, sc);
    }
    smax = wmax(smax);

    // pass 3: exp-weighted accumulation
    float ssum = 0.f;
    float4 acc = make_float4(0.f, 0.f, 0.f, 0.f);
    for (int e = s0; e < s1; e++) {
        int s = g_csr[e];
        float sc = qd + g_hdot[s];
        sc = sc > 0.f ? sc : 0.2f * sc;
        float es = __expf(sc - smax);
        ssum += es;
        float4 hv = H4[(size_t)s * 32 + lane];
        acc.x = fmaf(es, hv.x, acc.x); acc.y = fmaf(es, hv.y, acc.y);
        acc.z = fmaf(es, hv.z, acc.z); acc.w = fmaf(es, hv.w, acc.w);
    }
    float inv = 1.f / ssum;
    ((float4*)g_xc)[(size_t)w * 32 + lane] =
        make_float4(acc.x * inv, acc.y * inv, acc.z * inv, acc.w * inv);
}

// ---------------- LEConv node scalars (warp per node; scalar weight loads) ----------------
__global__ void k_scal(const float* __restrict__ Wl1, const float* __restrict__ bl1,
                       const float* __restrict__ Wl2, const float* __restrict__ Wl3,
                       const float* __restrict__ bl3) {
    int w = (blockIdx.x * blockDim.x + threadIdx.x) >> 5;
    int lane = threadIdx.x & 31;
    if (w >= N_NODES) return;
    float4 xv = ((const float4*)g_xc)[(size_t)w * 32 + lane];
    const float* p1 = Wl1 + lane * 4;
    const float* p2 = Wl2 + lane * 4;
    const float* p3 = Wl3 + lane * 4;
    float d1 = wsum(xv.x * p1[0] + xv.y * p1[1] + xv.z * p1[2] + xv.w * p1[3]);
    float d2 = wsum(xv.x * p2[0] + xv.y * p2[1] + xv.z * p2[2] + xv.w * p2[3]);
    float d3 = wsum(xv.x * p3[0] + xv.y * p3[1] + xv.z * p3[2] + xv.w * p3[3]);
    if (lane == 0) {
        g_a[w] = d1 + bl1[0];
        g_fitp[w] = d3 + bl3[0] - (float)g_deg[w] * d2;
    }
}

// fit[i] = sigmoid(fitp[i] + sum_{e: dst=i} a[src[e]])  (warp per node)
__global__ void k_fit() {
    int w = (blockIdx.x * blockDim.x + threadIdx.x) >> 5;
    int lane = threadIdx.x & 31;
    if (w >= N_NODES) return;
    int s0 = g_off[w], s1 = g_off[w + 1];
    float sum = 0.f;
    for (int e = s0 + lane; e < s1; e += 32) sum += g_a[g_csr[e]];
    sum = wsum(sum);
    if (lane == 0) g_fit[w] = 1.f / (1.f + __expf(-(g_fitp[w] + sum)));
}

// ---------------- per-graph top-K select + weighted row-sum ----------------
__global__ void k_topk() {
    int g = blockIdx.x;
    __shared__ float key[NPG];
    __shared__ int   sidx[NPG];
    __shared__ float part[256];
    int t = threadIdx.x;  // 256
    for (int i = t; i < NPG; i += 256) { key[i] = g_fit[g * NPG + i]; sidx[i] = i; }
    __syncthreads();
    // bitonic sort, descending by value, ties -> smaller index first (matches top_k)
    for (int k = 2; k <= NPG; k <<= 1) {
        for (int j = k >> 1; j > 0; j >>= 1) {
            int i = ((t & ~(j - 1)) << 1) | (t & (j - 1));
            int l = i | j;
            float ki = key[i], kl = key[l];
            int ii = sidx[i], il = sidx[l];
            bool up = ((i & k) == 0);
            bool lBetter = (kl > ki) || (kl == ki && il < ii);
            if (up == lBetter) { key[i] = kl; key[l] = ki; sidx[i] = il; sidx[l] = ii; }
            __syncthreads();
        }
    }
    // S[g] = sum over top-K of fit * xc[row]
    float acc = 0.f;
    int ch = t & 127, half = t >> 7;
    for (int r = half * 128; r < half * 128 + 128; r++) {
        int node = g * NPG + sidx[r];
        acc = fmaf(key[r], g_xc[(size_t)node * C + ch], acc);
    }
    part[t] = acc;
    __syncthreads();
    if (t < 128) g_S[g * C + t] = part[t] + part[t + 128];
}

// out[g] = (S[g]/K) @ W2 + b2
__global__ void k_final(const float* __restrict__ W2, const float* __restrict__ b2,
                        float* __restrict__ out) {
    int g = blockIdx.x, t = threadIdx.x;  // 128
    __shared__ float s[C];
    s[t] = g_S[g * C + t] * (1.0f / (float)KSEL);
    __syncthreads();
    float acc = b2[t];
    #pragma unroll 4
    for (int c = 0; c < C; c++) acc = fmaf(s[c], W2[c * C + t], acc);
    out[g * C + t] = acc;
}

// ---------------- launcher ----------------
extern "C" void kernel_launch(void* const* d_in, const int* in_sizes, int n_in,
                              void* d_out, int out_size) {
    const float* x   = (const float*)d_in[0];
    const float* W1  = (const float*)d_in[1];
    const float* b1  = (const float*)d_in[2];
    const float* Wp  = (const float*)d_in[3];
    const float* bp  = (const float*)d_in[4];
    const float* Wa  = (const float*)d_in[5];
    const float* ba  = (const float*)d_in[6];
    const float* Wl1 = (const float*)d_in[7];
    const float* bl1 = (const float*)d_in[8];
    const float* Wl2 = (const float*)d_in[9];
    const float* Wl3 = (const float*)d_in[10];
    const float* bl3 = (const float*)d_in[11];
    const float* W2  = (const float*)d_in[12];
    const float* b2  = (const float*)d_in[13];
    const int*   ei  = (const int*)d_in[14];   // int32! (JAX x64 disabled)
    int E = in_sizes[14] / 2;
    float* out = (float*)d_out;

    k_zero<<<N_NODES / 256, 256>>>();
    k_prep<<<1, 128>>>(Wp, bp, Wa, ba);
    k_gemm_relu<<<N_NODES / 128, 256>>>(x, W1, b1);
    k_hdot<<<N_NODES / 8, 256>>>(Wa);
    k_hist<<<(E + 255) / 256, 256>>>(ei, E);
    k_scan<<<1, 1024>>>();
    k_scatter<<<(E + 255) / 256, 256>>>(ei, E);
    k_atten<<<N_NODES / 8, 256>>>();
    k_scal<<<N_NODES / 8, 256>>>(Wl1, bl1, Wl2, Wl3, bl3);
    k_fit<<<N_NODES / 8, 256>>>();
    k_topk<<<BGR, 256>>>();
    k_final<<<BGR, 128>>>(W2, b2, out);
}

// round 5
// speedup vs baseline: 1.5016x; 1.5016x over previous
#include <cuda_runtime.h>

#define N_NODES 65536
#define C 128
#define BGR 128
#define NPG 512
#define KSEL 256
#define DEG 16
#define E_RAND_PG (NPG * DEG)      // 8192 random edges per graph
#define E_LOC (E_RAND_PG + NPG)    // + self loops = 8704
#define THREADS 512
#define NWARP 16
#define CHUNK 64                   // channels per smem tile chunk

// ---------------- device scratch ----------------
__device__ __align__(16) float g_h[N_NODES * C];   // relu(x@W1+b1)
__device__ __align__(16) float g_xc[N_NODES * C];  // cluster reps
__device__ __align__(16) float g_v[C];             // Wp @ Wa[:128]
__device__ float g_c;                              // bp.Wa[:128] + ba

__device__ __forceinline__ float wsum(float v) {
    #pragma unroll
    for (int o = 16; o > 0; o >>= 1) v += __shfl_xor_sync(0xffffffffu, v, o);
    return v;
}
__device__ __forceinline__ float wmax(float v) {
    #pragma unroll
    for (int o = 16; o > 0; o >>= 1) v = fmaxf(v, __shfl_xor_sync(0xffffffffu, v, o));
    return v;
}
__device__ __forceinline__ float hsum16(float v) {  // reduce within 16-lane half
    #pragma unroll
    for (int o = 8; o > 0; o >>= 1) v += __shfl_xor_sync(0xffffffffu, v, o);
    return v;
}

// v[k] = sum_j Wp[k,j]*Wa[j];  c = bp.Wa[:128] + ba
__global__ void k_prep(const float* __restrict__ Wp, const float* __restrict__ bp,
                       const float* __restrict__ Wa, const float* __restrict__ ba) {
    int t = threadIdx.x;  // 128
    float s = 0.f;
    #pragma unroll 4
    for (int j = 0; j < C; j++) s += Wp[t * C + j] * Wa[j];
    g_v[t] = s;
    __shared__ float red[C];
    red[t] = bp[t] * Wa[t];
    __syncthreads();
    for (int o = 64; o > 0; o >>= 1) {
        if (t < o) red[t] += red[t + o];
        __syncthreads();
    }
    if (t == 0) g_c = red[0] + ba[0];
}

// ---------------- h = relu(x @ W1 + b1) ----------------
__global__ void k_gemm_relu(const float* __restrict__ X, const float* __restrict__ W,
                            const float* __restrict__ bias) {
    __shared__ float Xs[16][128];
    __shared__ float Ws[16][128];
    int tid = threadIdx.x;
    int tx = tid & 15, ty = tid >> 4;
    int row0 = blockIdx.x * 128;
    float acc[8][8];
    #pragma unroll
    for (int j = 0; j < 8; j++)
        #pragma unroll
        for (int i = 0; i < 8; i++) acc[j][i] = 0.f;

    for (int k0 = 0; k0 < C; k0 += 16) {
        #pragma unroll
        for (int u = 0; u < 2; u++) {
            int f = tid * 2 + u;
            int r = f >> 2, c4 = (f & 3) * 4;
            float4 xv = *(const float4*)&X[(size_t)(row0 + r) * C + k0 + c4];
            Xs[c4 + 0][r] = xv.x; Xs[c4 + 1][r] = xv.y;
            Xs[c4 + 2][r] = xv.z; Xs[c4 + 3][r] = xv.w;
            int rw = f >> 5, cw = (f & 31) * 4;
            Ws[rw][cw + 0] = W[(size_t)(k0 + rw) * C + cw + 0];
            Ws[rw][cw + 1] = W[(size_t)(k0 + rw) * C + cw + 1];
            Ws[rw][cw + 2] = W[(size_t)(k0 + rw) * C + cw + 2];
            Ws[rw][cw + 3] = W[(size_t)(k0 + rw) * C + cw + 3];
        }
        __syncthreads();
        #pragma unroll
        for (int kk = 0; kk < 16; kk++) {
            float a[8], b[8];
            #pragma unroll
            for (int j = 0; j < 8; j++) a[j] = Xs[kk][ty * 8 + j];
            #pragma unroll
            for (int i = 0; i < 8; i++) b[i] = Ws[kk][tx + 16 * i];
            #pragma unroll
            for (int j = 0; j < 8; j++)
                #pragma unroll
                for (int i = 0; i < 8; i++) acc[j][i] = fmaf(a[j], b[i], acc[j][i]);
        }
        __syncthreads();
    }
    #pragma unroll
    for (int j = 0; j < 8; j++) {
        int row = row0 + ty * 8 + j;
        #pragma unroll
        for (int i = 0; i < 8; i++) {
            int col = tx + 16 * i;
            float r = acc[j][i] + bias[col];
            g_h[(size_t)row * C + col] = r > 0.f ? r : 0.f;
        }
    }
}

// ---------------- mega kernel: one block per graph ----------------
// smem layout (dynamic):
//  tile   [NPG*CHUNK] f       131072 B
//  hdot,qd,smax,sinv,f1,f2,f3,fit : 8 x [NPG] f = 16384 B
//  off    [NPG+2] i             2056 B
//  cur    [NPG] i               2048 B  (reused as sidx)
//  csr    [E_LOC] u16          17408 B
#define SM_BYTES (131072 + 2048*8 + 2056 + 2048 + 17408)

extern "C" __global__ void __launch_bounds__(THREADS, 1)
k_mega(const int* __restrict__ ei, int E,
       const float* __restrict__ Wa,
       const float* __restrict__ Wl1, const float* __restrict__ bl1,
       const float* __restrict__ Wl2,
       const float* __restrict__ Wl3, const float* __restrict__ bl3,
       const float* __restrict__ W2, const float* __restrict__ b2,
       float* __restrict__ out) {
    extern __shared__ char sm[];
    float* tile = (float*)sm;                         // [NPG][CHUNK]
    float* hdot = tile + NPG * CHUNK;
    float* qd   = hdot + NPG;
    float* smax = qd + NPG;
    float* sinv = smax + NPG;
    float* f1   = sinv + NPG;
    float* f2   = f1 + NPG;
    float* f3   = f2 + NPG;
    float* fit  = f3 + NPG;
    int*   off  = (int*)(fit + NPG);                  // [NPG+2]
    int*   cur  = off + NPG + 2;                      // [NPG]
    unsigned short* csr = (unsigned short*)(cur + NPG);  // [E_LOC]

    const int g = blockIdx.x;
    const int base = g * NPG;
    const int tid = threadIdx.x;
    const int wid = tid >> 5;
    const int lane = tid & 31;

    // ---- local CSR build ----
    cur[tid] = 1;  // self loop pre-counted
    __syncthreads();
    for (int e = tid; e < E_RAND_PG; e += THREADS) {
        int dst = ei[(size_t)E + base * DEG + e] - base;
        atomicAdd(&cur[dst], 1);
    }
    __syncthreads();
    // inclusive scan of cur -> off[t+1]
    for (int d = 1; d < THREADS; d <<= 1) {
        int v = (tid >= d) ? cur[tid - d] : 0;
        __syncthreads();
        cur[tid] += v;
        __syncthreads();
    }
    off[tid + 1] = cur[tid];
    if (tid == 0) off[0] = 0;
    __syncthreads();
    cur[tid] = 0;
    __syncthreads();
    // scatter random edges
    for (int e = tid; e < E_RAND_PG; e += THREADS) {
        int dst = ei[(size_t)E + base * DEG + e] - base;
        int src = ei[base * DEG + e] - base;
        int p = off[dst] + atomicAdd(&cur[dst], 1);
        csr[p] = (unsigned short)src;
    }
    __syncthreads();
    // self loops
    {
        int p = off[tid] + atomicAdd(&cur[tid], 1);
        csr[p] = (unsigned short)tid;
    }
    __syncthreads();

    const float gc = g_c;

    // ==== phase A: qd partial per chunk (+hdot during tile load) ====
    #pragma unroll
    for (int c = 0; c < 2; c++) {
        // tile load: half-warp per row, + hdot partial
        {
            int half = lane >> 4, l16 = lane & 15;
            int cl = l16 * 4;
            const float* wa2 = Wa + C + c * CHUNK;
            for (int r2 = 0; r2 < 16; r2++) {
                int row = wid * 32 + r2 * 2 + half;
                const float* hp = g_h + (size_t)(base + row) * C + c * CHUNK + cl;
                float4 hv = *(const float4*)hp;
                float* tp = tile + row * CHUNK + cl;
                tp[0] = hv.x; tp[1] = hv.y; tp[2] = hv.z; tp[3] = hv.w;
                float p = hv.x * wa2[cl] + hv.y * wa2[cl + 1] +
                          hv.z * wa2[cl + 2] + hv.w * wa2[cl + 3];
                p = hsum16(p);
                if (l16 == 0) {
                    if (c == 0) hdot[row] = p; else hdot[row] += p;
                }
            }
        }
        __syncthreads();
        // qd sweep: warp per node, vector max over nbrs then dot with v chunk
        {
            float vx = g_v[c * CHUNK + lane * 2];
            float vy = g_v[c * CHUNK + lane * 2 + 1];
            for (int n = wid; n < NPG; n += NWARP) {
                int s0 = off[n], s1 = off[n + 1];
                float mx = 0.f, my = 0.f;  // h >= 0
                for (int e = s0; e < s1; e++) {
                    int s = csr[e];
                    float2 hv = *(const float2*)(tile + s * CHUNK + lane * 2);
                    mx = fmaxf(mx, hv.x); my = fmaxf(my, hv.y);
                }
                float p = wsum(mx * vx + my * vy);
                if (lane == 0) { if (c == 0) qd[n] = p; else qd[n] += p; }
            }
        }
        __syncthreads();
    }

    // ==== phase B: scalar softmax stats ====
    for (int n = wid; n < NPG; n += NWARP) {
        int s0 = off[n], s1 = off[n + 1];
        float mh = -3.0e38f;
        for (int e = s0 + lane; e < s1; e += 32) mh = fmaxf(mh, hdot[csr[e]]);
        mh = wmax(mh);
        float q = qd[n] + gc;
        float sm = q + mh;
        sm = sm > 0.f ? sm : 0.2f * sm;   // leaky monotone -> max of scores
        float ss = 0.f;
        for (int e = s0 + lane; e < s1; e += 32) {
            float sc = q + hdot[csr[e]];
            sc = sc > 0.f ? sc : 0.2f * sc;
            ss += __expf(sc - sm);
        }
        ss = wsum(ss);
        if (lane == 0) { qd[n] = q; smax[n] = sm; sinv[n] = 1.f / ss; }
    }
    __syncthreads();

    // ==== phase C: weighted accumulation; chunk1 first (tile resident), then chunk0 ====
    #pragma unroll
    for (int cc = 0; cc < 2; cc++) {
        int c = 1 - cc;
        if (cc == 1) {  // reload chunk0 tile
            int half = lane >> 4, l16 = lane & 15;
            int cl = l16 * 4;
            for (int r2 = 0; r2 < 16; r2++) {
                int row = wid * 32 + r2 * 2 + half;
                const float* hp = g_h + (size_t)(base + row) * C + c * CHUNK + cl;
                float4 hv = *(const float4*)hp;
                float* tp = tile + row * CHUNK + cl;
                tp[0] = hv.x; tp[1] = hv.y; tp[2] = hv.z; tp[3] = hv.w;
            }
            __syncthreads();
        }
        float w1x = Wl1[c * CHUNK + lane * 2], w1y = Wl1[c * CHUNK + lane * 2 + 1];
        float w2x = Wl2[c * CHUNK + lane * 2], w2y = Wl2[c * CHUNK + lane * 2 + 1];
        float w3x = Wl3[c * CHUNK + lane * 2], w3y = Wl3[c * CHUNK + lane * 2 + 1];
        for (int n = wid; n < NPG; n += NWARP) {
            int s0 = off[n], s1 = off[n + 1];
            float q = qd[n], sm = smax[n], iv = sinv[n];
            float ax = 0.f, ay = 0.f;
            for (int e = s0; e < s1; e++) {
                int s = csr[e];
                float sc = q + hdot[s];
                sc = sc > 0.f ? sc : 0.2f * sc;
                float es = __expf(sc - sm);
                float2 hv = *(const float2*)(tile + s * CHUNK + lane * 2);
                ax = fmaf(es, hv.x, ax); ay = fmaf(es, hv.y, ay);
            }
            ax *= iv; ay *= iv;
            float2* xp = (float2*)(g_xc + (size_t)(base + n) * C + c * CHUNK);
            xp[lane] = make_float2(ax, ay);
            float d1 = wsum(ax * w1x + ay * w1y);
            float d2 = wsum(ax * w2x + ay * w2y);
            float d3 = wsum(ax * w3x + ay * w3y);
            if (lane == 0) {
                if (cc == 0) { f1[n] = d1; f2[n] = d2; f3[n] = d3; }
                else { f1[n] += d1; f2[n] += d2; f3[n] += d3; }
            }
        }
        __syncthreads();
    }

    // ==== phase D: LEConv fitness ====
    {
        float deg = (float)(off[tid + 1] - off[tid]);
        f1[tid] = f1[tid] + bl1[0];                       // a[node]
        f3[tid] = f3[tid] + bl3[0] - deg * f2[tid];       // fitp
    }
    __syncthreads();
    for (int n = wid; n < NPG; n += NWARP) {
        int s0 = off[n], s1 = off[n + 1];
        float s = 0.f;
        for (int e = s0 + lane; e < s1; e += 32) s += f1[csr[e]];
        s = wsum(s);
        if (lane == 0) fit[n] = 1.f / (1.f + __expf(-(f3[n] + s)));
    }
    __syncthreads();

    // ==== phase E: top-K via bitonic sort (desc, tie -> smaller index) ====
    int* sidx = cur;  // reuse
    sidx[tid] = tid;
    __syncthreads();
    for (int k = 2; k <= NPG; k <<= 1) {
        for (int j = k >> 1; j > 0; j >>= 1) {
            if (tid < NPG / 2) {
                int i = ((tid & ~(j - 1)) << 1) | (tid & (j - 1));
                int l = i | j;
                float ki = fit[i], kl = fit[l];
                int ii = sidx[i], il = sidx[l];
                bool up = ((i & k) == 0);
                bool lBetter = (kl > ki) || (kl == ki && il < ii);
                if (up == lBetter) {
                    fit[i] = kl; fit[l] = ki; sidx[i] = il; sidx[l] = ii;
                }
            }
            __syncthreads();
        }
    }

    // ==== phase F: S = sum_topK fit*xc ; out = (S/K)@W2 + b2 ====
    {
        int ch = tid & 127, grp = tid >> 7;  // 4 groups x 64 rows
        float acc = 0.f;
        for (int r = grp * 64; r < grp * 64 + 64; r++) {
            int node = sidx[r];
            acc = fmaf(fit[r], g_xc[(size_t)(base + node) * C + ch], acc);
        }
        tile[tid] = acc;
    }
    __syncthreads();
    if (tid < C) {
        float s = (tile[tid] + tile[128 + tid] + tile[256 + tid] + tile[384 + tid])
                  * (1.f / (float)KSEL);
        qd[tid] = s;  // reuse as s[] buffer
    }
    __syncthreads();
    if (tid < C) {
        float acc = b2[tid];
        #pragma unroll 4
        for (int c = 0; c < C; c++) acc = fmaf(qd[c], W2[c * C + tid], acc);
        out[g * C + tid] = acc;
    }
}

// ---------------- launcher ----------------
extern "C" void kernel_launch(void* const* d_in, const int* in_sizes, int n_in,
                              void* d_out, int out_size) {
    const float* x   = (const float*)d_in[0];
    const float* W1  = (const float*)d_in[1];
    const float* b1  = (const float*)d_in[2];
    const float* Wp  = (const float*)d_in[3];
    const float* bp  = (const float*)d_in[4];
    const float* Wa  = (const float*)d_in[5];
    const float* ba  = (const float*)d_in[6];
    const float* Wl1 = (const float*)d_in[7];
    const float* bl1 = (const float*)d_in[8];
    const float* Wl2 = (const float*)d_in[9];
    const float* Wl3 = (const float*)d_in[10];
    const float* bl3 = (const float*)d_in[11];
    const float* W2  = (const float*)d_in[12];
    const float* b2  = (const float*)d_in[13];
    const int*   ei  = (const int*)d_in[14];   // int32 (JAX x64 disabled)
    int E = in_sizes[14] / 2;
    float* out = (float*)d_out;

    cudaFuncSetAttribute(k_mega, cudaFuncAttributeMaxDynamicSharedMemorySize,
                         SM_BYTES);

    k_prep<<<1, 128>>>(Wp, bp, Wa, ba);
    k_gemm_relu<<<N_NODES / 128, 256>>>(x, W1, b1);
    k_mega<<<BGR, THREADS, SM_BYTES>>>(ei, E, Wa, Wl1, bl1, Wl2, Wl3, bl3,
                                       W2, b2, out);
}

// round 6
// speedup vs baseline: 1.6694x; 1.1117x over previous
#include <cuda_runtime.h>

#define N_NODES 65536
#define C 128
#define BGR 128
#define NPG 512
#define KSEL 256
#define DEG 16
#define E_RAND_PG (NPG * DEG)      // 8192 random edges per graph
#define E_LOC (E_RAND_PG + NPG)    // + self loops = 8704
#define THREADS 512
#define NWARP 16
#define CHUNK 64                   // channels per smem tile chunk

// ---------------- device scratch ----------------
__device__ __align__(16) float g_h[N_NODES * C];   // relu(x@W1+b1)
__device__ __align__(16) float g_xc[N_NODES * C];  // cluster reps
__device__ __align__(16) float g_v[C];             // Wp @ Wa[:128]
__device__ float g_c;                              // bp.Wa[:128] + ba

__device__ __forceinline__ float wsum(float v) {
    #pragma unroll
    for (int o = 16; o > 0; o >>= 1) v += __shfl_xor_sync(0xffffffffu, v, o);
    return v;
}
__device__ __forceinline__ float wmax(float v) {
    #pragma unroll
    for (int o = 16; o > 0; o >>= 1) v = fmaxf(v, __shfl_xor_sync(0xffffffffu, v, o));
    return v;
}
__device__ __forceinline__ float hsum16(float v) {
    #pragma unroll
    for (int o = 8; o > 0; o >>= 1) v += __shfl_xor_sync(0xffffffffu, v, o);
    return v;
}

// one block per output element; coalesced row reads
__global__ void k_prep(const float* __restrict__ Wp, const float* __restrict__ bp,
                       const float* __restrict__ Wa, const float* __restrict__ ba) {
    int k = blockIdx.x, t = threadIdx.x;  // 128 blocks x 128 threads
    __shared__ float red[4], red2[4];
    int w = t >> 5, lane = t & 31;
    float p = Wp[k * C + t] * Wa[t];
    float s = wsum(p);
    if (lane == 0) red[w] = s;
    if (k == 0) {
        float q = wsum(bp[t] * Wa[t]);
        if (lane == 0) red2[w] = q;
    }
    __syncthreads();
    if (t == 0) {
        g_v[k] = red[0] + red[1] + red[2] + red[3];
        if (k == 0) g_c = red2[0] + red2[1] + red2[2] + red2[3] + ba[0];
    }
}

// ---------------- h = relu(x @ W1 + b1) ----------------
// thread (tx,ty) owns rows ty*8..+7, cols tx*8..+7 (contiguous -> coalesced stores)
__global__ void k_gemm_relu(const float* __restrict__ X, const float* __restrict__ W,
                            const float* __restrict__ bias) {
    __shared__ float Xs[16][128];
    __shared__ float Ws[16][128];
    int tid = threadIdx.x;
    int tx = tid & 15, ty = tid >> 4;
    int row0 = blockIdx.x * 128;
    float acc[8][8];
    #pragma unroll
    for (int j = 0; j < 8; j++)
        #pragma unroll
        for (int i = 0; i < 8; i++) acc[j][i] = 0.f;

    for (int k0 = 0; k0 < C; k0 += 16) {
        #pragma unroll
        for (int u = 0; u < 2; u++) {
            int f = tid * 2 + u;
            int r = f >> 2, c4 = (f & 3) * 4;
            float4 xv = *(const float4*)&X[(size_t)(row0 + r) * C + k0 + c4];
            Xs[c4 + 0][r] = xv.x; Xs[c4 + 1][r] = xv.y;
            Xs[c4 + 2][r] = xv.z; Xs[c4 + 3][r] = xv.w;
            int rw = f >> 5, cw = (f & 31) * 4;
            Ws[rw][cw + 0] = W[(size_t)(k0 + rw) * C + cw + 0];
            Ws[rw][cw + 1] = W[(size_t)(k0 + rw) * C + cw + 1];
            Ws[rw][cw + 2] = W[(size_t)(k0 + rw) * C + cw + 2];
            Ws[rw][cw + 3] = W[(size_t)(k0 + rw) * C + cw + 3];
        }
        __syncthreads();
        #pragma unroll
        for (int kk = 0; kk < 16; kk++) {
            float a[8], b[8];
            #pragma unroll
            for (int j = 0; j < 8; j++) a[j] = Xs[kk][ty * 8 + j];
            #pragma unroll
            for (int i = 0; i < 8; i++) b[i] = Ws[kk][tx * 8 + i];
            #pragma unroll
            for (int j = 0; j < 8; j++)
                #pragma unroll
                for (int i = 0; i < 8; i++) acc[j][i] = fmaf(a[j], b[i], acc[j][i]);
        }
        __syncthreads();
    }
    #pragma unroll
    for (int j = 0; j < 8; j++) {
        int row = row0 + ty * 8 + j;
        float r0 = acc[j][0] + bias[tx * 8 + 0];
        float r1 = acc[j][1] + bias[tx * 8 + 1];
        float r2 = acc[j][2] + bias[tx * 8 + 2];
        float r3 = acc[j][3] + bias[tx * 8 + 3];
        float r4 = acc[j][4] + bias[tx * 8 + 4];
        float r5 = acc[j][5] + bias[tx * 8 + 5];
        float r6 = acc[j][6] + bias[tx * 8 + 6];
        float r7 = acc[j][7] + bias[tx * 8 + 7];
        float4* dp = (float4*)(g_h + (size_t)row * C + tx * 8);
        dp[0] = make_float4(fmaxf(r0, 0.f), fmaxf(r1, 0.f), fmaxf(r2, 0.f), fmaxf(r3, 0.f));
        dp[1] = make_float4(fmaxf(r4, 0.f), fmaxf(r5, 0.f), fmaxf(r6, 0.f), fmaxf(r7, 0.f));
    }
}

// ---------------- mega kernel: one block per graph ----------------
// smem: tile 131072 | 8 scalar arrays 16384 | off 2056 | cur 2048 | alpha 34816 | csr 17408
#define SM_BYTES (131072 + 2048*8 + 2056 + 2048 + 34816 + 17408)

extern "C" __global__ void __launch_bounds__(THREADS, 1)
k_mega(const int* __restrict__ ei, int E,
       const float* __restrict__ Wa,
       const float* __restrict__ Wl1, const float* __restrict__ bl1,
       const float* __restrict__ Wl2,
       const float* __restrict__ Wl3, const float* __restrict__ bl3,
       const float* __restrict__ W2, const float* __restrict__ b2,
       float* __restrict__ out) {
    extern __shared__ char sm[];
    float* tile = (float*)sm;                         // [NPG][CHUNK]
    float* hdot = tile + NPG * CHUNK;
    float* qd   = hdot + NPG;
    float* smax = qd + NPG;
    float* sinv = smax + NPG;
    float* f1   = sinv + NPG;
    float* f2   = f1 + NPG;
    float* f3   = f2 + NPG;
    float* fit  = f3 + NPG;
    int*   off  = (int*)(fit + NPG);                  // [NPG+2]
    int*   cur  = off + NPG + 2;                      // [NPG]
    float* alpha = (float*)(cur + NPG);               // [E_LOC]
    unsigned short* csr = (unsigned short*)(alpha + E_LOC);  // [E_LOC]

    const int g = blockIdx.x;
    const int base = g * NPG;
    const int tid = threadIdx.x;
    const int wid = tid >> 5;
    const int lane = tid & 31;

    // ---- local CSR build ----
    cur[tid] = 1;  // self loop pre-counted
    __syncthreads();
    for (int e = tid; e < E_RAND_PG; e += THREADS) {
        int dst = ei[(size_t)E + base * DEG + e] - base;
        atomicAdd(&cur[dst], 1);
    }
    __syncthreads();
    for (int d = 1; d < THREADS; d <<= 1) {
        int v = (tid >= d) ? cur[tid - d] : 0;
        __syncthreads();
        cur[tid] += v;
        __syncthreads();
    }
    off[tid + 1] = cur[tid];
    if (tid == 0) off[0] = 0;
    __syncthreads();
    cur[tid] = 0;
    __syncthreads();
    for (int e = tid; e < E_RAND_PG; e += THREADS) {
        int dst = ei[(size_t)E + base * DEG + e] - base;
        int src = ei[base * DEG + e] - base;
        int p = off[dst] + atomicAdd(&cur[dst], 1);
        csr[p] = (unsigned short)src;
    }
    __syncthreads();
    {
        int p = off[tid] + atomicAdd(&cur[tid], 1);
        csr[p] = (unsigned short)tid;
    }
    __syncthreads();

    const float gc = g_c;

    // ==== phase A: per-chunk tile load (+hdot) then qd max-dot sweep ====
    #pragma unroll
    for (int c = 0; c < 2; c++) {
        {
            int half = lane >> 4, l16 = lane & 15;
            int cl = l16 * 4;
            const float* wa2 = Wa + C + c * CHUNK;
            for (int r2 = 0; r2 < 16; r2++) {
                int row = wid * 32 + r2 * 2 + half;
                const float* hp = g_h + (size_t)(base + row) * C + c * CHUNK + cl;
                float4 hv = *(const float4*)hp;
                float* tp = tile + row * CHUNK + cl;
                tp[0] = hv.x; tp[1] = hv.y; tp[2] = hv.z; tp[3] = hv.w;
                float p = hv.x * wa2[cl] + hv.y * wa2[cl + 1] +
                          hv.z * wa2[cl + 2] + hv.w * wa2[cl + 3];
                p = hsum16(p);
                if (l16 == 0) {
                    if (c == 0) hdot[row] = p; else hdot[row] += p;
                }
            }
        }
        __syncthreads();
        {
            float vx = g_v[c * CHUNK + lane * 2];
            float vy = g_v[c * CHUNK + lane * 2 + 1];
            for (int n = wid; n < NPG; n += NWARP) {
                int s0 = off[n], s1 = off[n + 1];
                float mx = 0.f, my = 0.f;  // h >= 0
                for (int e = s0; e < s1; e++) {
                    int s = csr[e];
                    float2 hv = *(const float2*)(tile + s * CHUNK + lane * 2);
                    mx = fmaxf(mx, hv.x); my = fmaxf(my, hv.y);
                }
                float p = wsum(mx * vx + my * vy);
                if (lane == 0) { if (c == 0) qd[n] = p; else qd[n] += p; }
            }
        }
        __syncthreads();
    }

    // ==== phase B: softmax stats + per-edge alpha cache ====
    for (int n = wid; n < NPG; n += NWARP) {
        int s0 = off[n], s1 = off[n + 1];
        float mh = -3.0e38f;
        for (int e = s0 + lane; e < s1; e += 32) mh = fmaxf(mh, hdot[csr[e]]);
        mh = wmax(mh);
        float q = qd[n] + gc;
        float sm = q + mh;
        sm = sm > 0.f ? sm : 0.2f * sm;   // leaky monotone -> max of scores
        float ss = 0.f;
        for (int e = s0 + lane; e < s1; e += 32) {
            float sc = q + hdot[csr[e]];
            sc = sc > 0.f ? sc : 0.2f * sc;
            float es = __expf(sc - sm);
            alpha[e] = es;
            ss += es;
        }
        ss = wsum(ss);
        if (lane == 0) sinv[n] = 1.f / ss;
    }
    __syncthreads();

    // ==== phase C: weighted accumulation from cached alpha ====
    #pragma unroll
    for (int cc = 0; cc < 2; cc++) {
        int c = 1 - cc;
        if (cc == 1) {  // reload chunk0 tile
            int half = lane >> 4, l16 = lane & 15;
            int cl = l16 * 4;
            for (int r2 = 0; r2 < 16; r2++) {
                int row = wid * 32 + r2 * 2 + half;
                const float* hp = g_h + (size_t)(base + row) * C + c * CHUNK + cl;
                float4 hv = *(const float4*)hp;
                float* tp = tile + row * CHUNK + cl;
                tp[0] = hv.x; tp[1] = hv.y; tp[2] = hv.z; tp[3] = hv.w;
            }
            __syncthreads();
        }
        float w1x = Wl1[c * CHUNK + lane * 2], w1y = Wl1[c * CHUNK + lane * 2 + 1];
        float w2x = Wl2[c * CHUNK + lane * 2], w2y = Wl2[c * CHUNK + lane * 2 + 1];
        float w3x = Wl3[c * CHUNK + lane * 2], w3y = Wl3[c * CHUNK + lane * 2 + 1];
        for (int n = wid; n < NPG; n += NWARP) {
            int s0 = off[n], s1 = off[n + 1];
            float iv = sinv[n];
            float ax = 0.f, ay = 0.f;
            for (int e = s0; e < s1; e++) {
                int s = csr[e];
                float es = alpha[e];
                float2 hv = *(const float2*)(tile + s * CHUNK + lane * 2);
                ax = fmaf(es, hv.x, ax); ay = fmaf(es, hv.y, ay);
            }
            ax *= iv; ay *= iv;
            float2* xp = (float2*)(g_xc + (size_t)(base + n) * C + c * CHUNK);
            xp[lane] = make_float2(ax, ay);
            float d1 = wsum(ax * w1x + ay * w1y);
            float d2 = wsum(ax * w2x + ay * w2y);
            float d3 = wsum(ax * w3x + ay * w3y);
            if (lane == 0) {
                if (cc == 0) { f1[n] = d1; f2[n] = d2; f3[n] = d3; }
                else { f1[n] += d1; f2[n] += d2; f3[n] += d3; }
            }
        }
        __syncthreads();
    }

    // ==== phase D: LEConv fitness ====
    {
        float deg = (float)(off[tid + 1] - off[tid]);
        f1[tid] = f1[tid] + bl1[0];
        f3[tid] = f3[tid] + bl3[0] - deg * f2[tid];
    }
    __syncthreads();
    for (int n = wid; n < NPG; n += NWARP) {
        int s0 = off[n], s1 = off[n + 1];
        float s = 0.f;
        for (int e = s0 + lane; e < s1; e += 32) s += f1[csr[e]];
        s = wsum(s);
        if (lane == 0) fit[n] = 1.f / (1.f + __expf(-(f3[n] + s)));
    }
    __syncthreads();

    // ==== phase E: bitonic sort (desc, tie -> smaller index) ====
    int* sidx = cur;
    sidx[tid] = tid;
    __syncthreads();
    for (int k = 2; k <= NPG; k <<= 1) {
        for (int j = k >> 1; j > 0; j >>= 1) {
            if (tid < NPG / 2) {
                int i = ((tid & ~(j - 1)) << 1) | (tid & (j - 1));
                int l = i | j;
                float ki = fit[i], kl = fit[l];
                int ii = sidx[i], il = sidx[l];
                bool up = ((i & k) == 0);
                bool lBetter = (kl > ki) || (kl == ki && il < ii);
                if (up == lBetter) {
                    fit[i] = kl; fit[l] = ki; sidx[i] = il; sidx[l] = ii;
                }
            }
            __syncthreads();
        }
    }

    // ==== phase F: S = sum_topK fit*xc ; out = (S/K)@W2 + b2 ====
    {
        int ch = tid & 127, grp = tid >> 7;
        float acc = 0.f;
        for (int r = grp * 64; r < grp * 64 + 64; r++) {
            int node = sidx[r];
            acc = fmaf(fit[r], g_xc[(size_t)(base + node) * C + ch], acc);
        }
        tile[tid] = acc;
    }
    __syncthreads();
    if (tid < C) {
        float s = (tile[tid] + tile[128 + tid] + tile[256 + tid] + tile[384 + tid])
                  * (1.f / (float)KSEL);
        qd[tid] = s;
    }
    __syncthreads();
    if (tid < C) {
        float acc = b2[tid];
        #pragma unroll 4
        for (int c = 0; c < C; c++) acc = fmaf(qd[c], W2[c * C + tid], acc);
        out[g * C + tid] = acc;
    }
}

// ---------------- launcher ----------------
extern "C" void kernel_launch(void* const* d_in, const int* in_sizes, int n_in,
                              void* d_out, int out_size) {
    const float* x   = (const float*)d_in[0];
    const float* W1  = (const float*)d_in[1];
    const float* b1  = (const float*)d_in[2];
    const float* Wp  = (const float*)d_in[3];
    const float* bp  = (const float*)d_in[4];
    const float* Wa  = (const float*)d_in[5];
    const float* ba  = (const float*)d_in[6];
    const float* Wl1 = (const float*)d_in[7];
    const float* bl1 = (const float*)d_in[8];
    const float* Wl2 = (const float*)d_in[9];
    const float* Wl3 = (const float*)d_in[10];
    const float* bl3 = (const float*)d_in[11];
    const float* W2  = (const float*)d_in[12];
    const float* b2  = (const float*)d_in[13];
    const int*   ei  = (const int*)d_in[14];   // int32 (JAX x64 disabled)
    int E = in_sizes[14] / 2;
    float* out = (float*)d_out;

    cudaFuncSetAttribute(k_mega, cudaFuncAttributeMaxDynamicSharedMemorySize,
                         SM_BYTES);

    k_gemm_relu<<<N_NODES / 128, 256>>>(x, W1, b1);
    k_prep<<<C, 128>>>(Wp, bp, Wa, ba);
    k_mega<<<BGR, THREADS, SM_BYTES>>>(ei, E, Wa, Wl1, bl1, Wl2, Wl3, bl3,
                                       W2, b2, out);
}

// round 7
// speedup vs baseline: 1.8581x; 1.1130x over previous
#include <cuda_runtime.h>

#define N_NODES 65536
#define C 128
#define BGR 128
#define NPG 512
#define KSEL 256
#define DEG 16
#define E_RAND_PG (NPG * DEG)      // 8192 random edges per graph
#define E_LOC (E_RAND_PG + NPG)    // + self loops = 8704
#define MT 1024                    // mega threads
#define CHUNK 64                   // channels per smem tile chunk
#define KT 16                      // gemm k-tile depth

// ---------------- device scratch ----------------
__device__ __align__(16) float g_h[N_NODES * C];
__device__ __align__(16) float g_xc[N_NODES * C];
__device__ __align__(16) float g_v[C];
__device__ float g_c;

__device__ __forceinline__ float wsum(float v) {
    #pragma unroll
    for (int o = 16; o > 0; o >>= 1) v += __shfl_xor_sync(0xffffffffu, v, o);
    return v;
}
__device__ __forceinline__ float wmax(float v) {
    #pragma unroll
    for (int o = 16; o > 0; o >>= 1) v = fmaxf(v, __shfl_xor_sync(0xffffffffu, v, o));
    return v;
}
__device__ __forceinline__ float hsum16(float v) {
    #pragma unroll
    for (int o = 8; o > 0; o >>= 1) v += __shfl_xor_sync(0xffffffffu, v, o);
    return v;
}

// packed f32x2 helpers (FFMA2 path — ptxas never emits from C++)
__device__ __forceinline__ unsigned long long pack2(float lo, float hi) {
    unsigned long long r;
    asm("mov.b64 %0, {%1, %2};" : "=l"(r) : "f"(lo), "f"(hi));
    return r;
}
__device__ __forceinline__ void unpack2(unsigned long long v, float& lo, float& hi) {
    asm("mov.b64 {%0, %1}, %2;" : "=f"(lo), "=f"(hi) : "l"(v));
}
__device__ __forceinline__ void fma2(unsigned long long& d, unsigned long long a,
                                     unsigned long long b) {
    asm("fma.rn.f32x2 %0, %1, %2, %0;" : "+l"(d) : "l"(a), "l"(b));
}

// one block per output element; coalesced row reads
__global__ void k_prep(const float* __restrict__ Wp, const float* __restrict__ bp,
                       const float* __restrict__ Wa, const float* __restrict__ ba) {
    int k = blockIdx.x, t = threadIdx.x;  // 128 x 128
    __shared__ float red[4], red2[4];
    int w = t >> 5, lane = t & 31;
    float s = wsum(Wp[k * C + t] * Wa[t]);
    if (lane == 0) red[w] = s;
    if (k == 0) {
        float q = wsum(bp[t] * Wa[t]);
        if (lane == 0) red2[w] = q;
    }
    __syncthreads();
    if (t == 0) {
        g_v[k] = red[0] + red[1] + red[2] + red[3];
        if (k == 0) g_c = red2[0] + red2[1] + red2[2] + red2[3] + ba[0];
    }
}

// ---------------- h = relu(x @ W1 + b1), packed f32x2, double-buffered ----------------
__global__ void __launch_bounds__(256)
k_gemm_relu(const float* __restrict__ X, const float* __restrict__ W,
            const float* __restrict__ bias) {
    __shared__ float Xs[2][KT][128];   // [k][row]
    __shared__ float Ws[2][KT][128];   // [k][col]
    int tid = threadIdx.x;
    int tx = tid & 15, ty = tid >> 4;
    int row0 = blockIdx.x * 128;

    unsigned long long acc2[8][4];
    #pragma unroll
    for (int j = 0; j < 8; j++)
        #pragma unroll
        for (int p = 0; p < 4; p++) acc2[j][p] = 0ULL;

    // tile loader
    #define LOAD_TILE(b, k0) do {                                              \
        _Pragma("unroll")                                                      \
        for (int u = 0; u < 2; u++) {                                          \
            int v = tid * 2 + u;                                               \
            int rx = v >> 2, kq = (v & 3) * 4;                                 \
            float4 xv = *(const float4*)&X[(size_t)(row0 + rx) * C + (k0) + kq]; \
            Xs[b][kq + 0][rx] = xv.x; Xs[b][kq + 1][rx] = xv.y;                \
            Xs[b][kq + 2][rx] = xv.z; Xs[b][kq + 3][rx] = xv.w;                \
            int kw = v >> 5, n4 = (v & 31) * 4;                                \
            Ws[b][kw][n4 + 0] = W[(size_t)((k0) + kw) * C + n4 + 0];           \
            Ws[b][kw][n4 + 1] = W[(size_t)((k0) + kw) * C + n4 + 1];           \
            Ws[b][kw][n4 + 2] = W[(size_t)((k0) + kw) * C + n4 + 2];           \
            Ws[b][kw][n4 + 3] = W[(size_t)((k0) + kw) * C + n4 + 3];           \
        }                                                                      \
    } while (0)

    LOAD_TILE(0, 0);
    __syncthreads();
    #pragma unroll
    for (int t = 0; t < C / KT; t++) {
        int cb = t & 1;
        if (t < C / KT - 1) LOAD_TILE(cb ^ 1, (t + 1) * KT);
        #pragma unroll
        for (int kk = 0; kk < KT; kk++) {
            float a[8], bb[8];
            *(float4*)&a[0]  = *(const float4*)&Xs[cb][kk][ty * 8];
            *(float4*)&a[4]  = *(const float4*)&Xs[cb][kk][ty * 8 + 4];
            *(float4*)&bb[0] = *(const float4*)&Ws[cb][kk][tx * 8];
            *(float4*)&bb[4] = *(const float4*)&Ws[cb][kk][tx * 8 + 4];
            unsigned long long b2[4];
            b2[0] = pack2(bb[0], bb[1]); b2[1] = pack2(bb[2], bb[3]);
            b2[2] = pack2(bb[4], bb[5]); b2[3] = pack2(bb[6], bb[7]);
            #pragma unroll
            for (int j = 0; j < 8; j++) {
                unsigned long long aj = pack2(a[j], a[j]);
                fma2(acc2[j][0], aj, b2[0]);
                fma2(acc2[j][1], aj, b2[1]);
                fma2(acc2[j][2], aj, b2[2]);
                fma2(acc2[j][3], aj, b2[3]);
            }
        }
        __syncthreads();
    }
    #undef LOAD_TILE

    float bs[8];
    #pragma unroll
    for (int i = 0; i < 8; i++) bs[i] = bias[tx * 8 + i];
    #pragma unroll
    for (int j = 0; j < 8; j++) {
        int row = row0 + ty * 8 + j;
        float r[8];
        unpack2(acc2[j][0], r[0], r[1]);
        unpack2(acc2[j][1], r[2], r[3]);
        unpack2(acc2[j][2], r[4], r[5]);
        unpack2(acc2[j][3], r[6], r[7]);
        float4* dp = (float4*)(g_h + (size_t)row * C + tx * 8);
        dp[0] = make_float4(fmaxf(r[0] + bs[0], 0.f), fmaxf(r[1] + bs[1], 0.f),
                            fmaxf(r[2] + bs[2], 0.f), fmaxf(r[3] + bs[3], 0.f));
        dp[1] = make_float4(fmaxf(r[4] + bs[4], 0.f), fmaxf(r[5] + bs[5], 0.f),
                            fmaxf(r[6] + bs[6], 0.f), fmaxf(r[7] + bs[7], 0.f));
    }
}

// ---------------- mega kernel: one block per graph, 1024 threads ----------------
#define SM_BYTES (131072 + 2048*8 + 2056 + 2048 + 34816 + 17408)

extern "C" __global__ void __launch_bounds__(MT, 1)
k_mega(const int* __restrict__ ei, int E,
       const float* __restrict__ Wa,
       const float* __restrict__ Wl1, const float* __restrict__ bl1,
       const float* __restrict__ Wl2,
       const float* __restrict__ Wl3, const float* __restrict__ bl3,
       const float* __restrict__ W2, const float* __restrict__ b2,
       float* __restrict__ out) {
    extern __shared__ char sm[];
    float* tile = (float*)sm;                         // [NPG][CHUNK]
    float* hdot = tile + NPG * CHUNK;
    float* qd   = hdot + NPG;
    float* smax = qd + NPG;
    float* sinv = smax + NPG;
    float* f1   = sinv + NPG;
    float* f2   = f1 + NPG;
    float* f3   = f2 + NPG;
    float* fit  = f3 + NPG;
    int*   off  = (int*)(fit + NPG);                  // [NPG+2]
    int*   cur  = off + NPG + 2;                      // [NPG]
    float* alpha = (float*)(cur + NPG);               // [E_LOC]
    unsigned short* csr = (unsigned short*)(alpha + E_LOC);  // [E_LOC]

    const int g = blockIdx.x;
    const int base = g * NPG;
    const int tid = threadIdx.x;
    const int wid = tid >> 5;
    const int lane = tid & 31;
    const int hw = tid >> 4;        // half-warp id 0..63
    const int l16 = tid & 15;
    const int ch4 = l16 * 4;        // float4 channel offset within chunk

    // ---- local CSR build ----
    if (tid < NPG) cur[tid] = 1;  // self loop pre-counted
    __syncthreads();
    for (int e = tid; e < E_RAND_PG; e += MT) {
        int dst = ei[(size_t)E + base * DEG + e] - base;
        atomicAdd(&cur[dst], 1);
    }
    __syncthreads();
    for (int d = 1; d < NPG; d <<= 1) {
        int v = 0;
        if (tid < NPG && tid >= d) v = cur[tid - d];
        __syncthreads();
        if (tid < NPG) cur[tid] += v;
        __syncthreads();
    }
    if (tid < NPG) off[tid + 1] = cur[tid];
    if (tid == 0) off[0] = 0;
    __syncthreads();
    if (tid < NPG) cur[tid] = 0;
    __syncthreads();
    for (int e = tid; e < E_RAND_PG; e += MT) {
        int dst = ei[(size_t)E + base * DEG + e] - base;
        int src = ei[base * DEG + e] - base;
        int p = off[dst] + atomicAdd(&cur[dst], 1);
        csr[p] = (unsigned short)src;
    }
    __syncthreads();
    if (tid < NPG) {
        int p = off[tid] + atomicAdd(&cur[tid], 1);
        csr[p] = (unsigned short)tid;
    }
    __syncthreads();

    const float gc = g_c;

    // ==== phase A: per-chunk tile load (+hdot partial) then qd max-dot sweep ====
    #pragma unroll
    for (int c = 0; c < 2; c++) {
        {
            const float* wa2 = Wa + C + c * CHUNK;
            float w0 = wa2[ch4], w1 = wa2[ch4 + 1], w2 = wa2[ch4 + 2], w3 = wa2[ch4 + 3];
            #pragma unroll
            for (int r = 0; r < 8; r++) {
                int row = hw + r * 64;
                float4 hv = *(const float4*)(g_h + (size_t)(base + row) * C + c * CHUNK + ch4);
                *(float4*)(tile + row * CHUNK + ch4) = hv;
                float p = hsum16(hv.x * w0 + hv.y * w1 + hv.z * w2 + hv.w * w3);
                if (l16 == 0) { if (c == 0) hdot[row] = p; else hdot[row] += p; }
            }
        }
        __syncthreads();
        {
            float4 vv = *(const float4*)(g_v + c * CHUNK + ch4);
            for (int n = hw; n < NPG; n += 64) {
                int s0 = off[n], s1 = off[n + 1];
                float4 m = make_float4(0.f, 0.f, 0.f, 0.f);  // h >= 0
                int e = s0;
                for (; e + 4 <= s1; e += 4) {
                    int i0 = csr[e], i1 = csr[e + 1], i2 = csr[e + 2], i3 = csr[e + 3];
                    float4 a0 = *(const float4*)(tile + i0 * CHUNK + ch4);
                    float4 a1 = *(const float4*)(tile + i1 * CHUNK + ch4);
                    float4 a2 = *(const float4*)(tile + i2 * CHUNK + ch4);
                    float4 a3 = *(const float4*)(tile + i3 * CHUNK + ch4);
                    m.x = fmaxf(fmaxf(fmaxf(m.x, a0.x), fmaxf(a1.x, a2.x)), a3.x);
                    m.y = fmaxf(fmaxf(fmaxf(m.y, a0.y), fmaxf(a1.y, a2.y)), a3.y);
                    m.z = fmaxf(fmaxf(fmaxf(m.z, a0.z), fmaxf(a1.z, a2.z)), a3.z);
                    m.w = fmaxf(fmaxf(fmaxf(m.w, a0.w), fmaxf(a1.w, a2.w)), a3.w);
                }
                for (; e < s1; e++) {
                    float4 a0 = *(const float4*)(tile + csr[e] * CHUNK + ch4);
                    m.x = fmaxf(m.x, a0.x); m.y = fmaxf(m.y, a0.y);
                    m.z = fmaxf(m.z, a0.z); m.w = fmaxf(m.w, a0.w);
                }
                float p = hsum16(m.x * vv.x + m.y * vv.y + m.z * vv.z + m.w * vv.w);
                if (l16 == 0) { if (c == 0) qd[n] = p; else qd[n] += p; }
            }
        }
        __syncthreads();
    }

    // ==== phase B: softmax stats + per-edge alpha cache (warp per node) ====
    for (int n = wid; n < NPG; n += 32) {
        int s0 = off[n], s1 = off[n + 1];
        float mh = -3.0e38f;
        for (int e = s0 + lane; e < s1; e += 32) mh = fmaxf(mh, hdot[csr[e]]);
        mh = wmax(mh);
        float q = qd[n] + gc;
        float sm = q + mh;
        sm = sm > 0.f ? sm : 0.2f * sm;   // leaky monotone -> max of scores
        float ss = 0.f;
        for (int e = s0 + lane; e < s1; e += 32) {
            float sc = q + hdot[csr[e]];
            sc = sc > 0.f ? sc : 0.2f * sc;
            float es = __expf(sc - sm);
            alpha[e] = es;
            ss += es;
        }
        ss = wsum(ss);
        if (lane == 0) sinv[n] = 1.f / ss;
    }
    __syncthreads();

    // ==== phase C: weighted accumulation from cached alpha (half-warp per node) ====
    #pragma unroll
    for (int cc = 0; cc < 2; cc++) {
        int c = 1 - cc;  // chunk1 is resident first
        if (cc == 1) {
            #pragma unroll
            for (int r = 0; r < 8; r++) {
                int row = hw + r * 64;
                float4 hv = *(const float4*)(g_h + (size_t)(base + row) * C + c * CHUNK + ch4);
                *(float4*)(tile + row * CHUNK + ch4) = hv;
            }
            __syncthreads();
        }
        float w10 = Wl1[c * CHUNK + ch4], w11 = Wl1[c * CHUNK + ch4 + 1],
              w12 = Wl1[c * CHUNK + ch4 + 2], w13 = Wl1[c * CHUNK + ch4 + 3];
        float w20 = Wl2[c * CHUNK + ch4], w21 = Wl2[c * CHUNK + ch4 + 1],
              w22 = Wl2[c * CHUNK + ch4 + 2], w23 = Wl2[c * CHUNK + ch4 + 3];
        float w30 = Wl3[c * CHUNK + ch4], w31 = Wl3[c * CHUNK + ch4 + 1],
              w32 = Wl3[c * CHUNK + ch4 + 2], w33 = Wl3[c * CHUNK + ch4 + 3];
        for (int n = hw; n < NPG; n += 64) {
            int s0 = off[n], s1 = off[n + 1];
            float iv = sinv[n];
            float ax = 0.f, ay = 0.f, az = 0.f, aw = 0.f;
            int e = s0;
            for (; e + 4 <= s1; e += 4) {
                int i0 = csr[e], i1 = csr[e + 1], i2 = csr[e + 2], i3 = csr[e + 3];
                float e0 = alpha[e], e1 = alpha[e + 1], e2 = alpha[e + 2], e3 = alpha[e + 3];
                float4 a0 = *(const float4*)(tile + i0 * CHUNK + ch4);
                float4 a1 = *(const float4*)(tile + i1 * CHUNK + ch4);
                float4 a2 = *(const float4*)(tile + i2 * CHUNK + ch4);
                float4 a3 = *(const float4*)(tile + i3 * CHUNK + ch4);
                ax = fmaf(e0, a0.x, fmaf(e1, a1.x, fmaf(e2, a2.x, fmaf(e3, a3.x, ax))));
                ay = fmaf(e0, a0.y, fmaf(e1, a1.y, fmaf(e2, a2.y, fmaf(e3, a3.y, ay))));
                az = fmaf(e0, a0.z, fmaf(e1, a1.z, fmaf(e2, a2.z, fmaf(e3, a3.z, az))));
                aw = fmaf(e0, a0.w, fmaf(e1, a1.w, fmaf(e2, a2.w, fmaf(e3, a3.w, aw))));
            }
            for (; e < s1; e++) {
                float e0 = alpha[e];
                float4 a0 = *(const float4*)(tile + csr[e] * CHUNK + ch4);
                ax = fmaf(e0, a0.x, ax); ay = fmaf(e0, a0.y, ay);
                az = fmaf(e0, a0.z, az); aw = fmaf(e0, a0.w, aw);
            }
            ax *= iv; ay *= iv; az *= iv; aw *= iv;
            *(float4*)(g_xc + (size_t)(base + n) * C + c * CHUNK + ch4) =
                make_float4(ax, ay, az, aw);
            float d1 = hsum16(ax * w10 + ay * w11 + az * w12 + aw * w13);
            float d2 = hsum16(ax * w20 + ay * w21 + az * w22 + aw * w23);
            float d3 = hsum16(ax * w30 + ay * w31 + az * w32 + aw * w33);
            if (l16 == 0) {
                if (cc == 0) { f1[n] = d1; f2[n] = d2; f3[n] = d3; }
                else { f1[n] += d1; f2[n] += d2; f3[n] += d3; }
            }
        }
        __syncthreads();
    }

    // ==== phase D: LEConv fitness ====
    if (tid < NPG) {
        float deg = (float)(off[tid + 1] - off[tid]);
        f1[tid] = f1[tid] + bl1[0];
        f3[tid] = f3[tid] + bl3[0] - deg * f2[tid];
    }
    __syncthreads();
    for (int n = wid; n < NPG; n += 32) {
        int s0 = off[n], s1 = off[n + 1];
        float s = 0.f;
        for (int e = s0 + lane; e < s1; e += 32) s += f1[csr[e]];
        s = wsum(s);
        if (lane == 0) fit[n] = 1.f / (1.f + __expf(-(f3[n] + s)));
    }
    __syncthreads();

    // ==== phase E: bitonic sort (desc, tie -> smaller index) ====
    int* sidx = cur;
    if (tid < NPG) sidx[tid] = tid;
    __syncthreads();
    for (int k = 2; k <= NPG; k <<= 1) {
        for (int j = k >> 1; j > 0; j >>= 1) {
            if (tid < NPG / 2) {
                int i = ((tid & ~(j - 1)) << 1) | (tid & (j - 1));
                int l = i | j;
                float ki = fit[i], kl = fit[l];
                int ii = sidx[i], il = sidx[l];
                bool up = ((i & k) == 0);
                bool lBetter = (kl > ki) || (kl == ki && il < ii);
                if (up == lBetter) {
                    fit[i] = kl; fit[l] = ki; sidx[i] = il; sidx[l] = ii;
                }
            }
            __syncthreads();
        }
    }

    // ==== phase F: S = sum_topK fit*xc ; out = (S/K)@W2 + b2 ====
    {
        int ch = tid & 127, grp = tid >> 7;  // 8 groups x 32 rows
        float acc = 0.f;
        for (int r = grp * 32; r < grp * 32 + 32; r++) {
            int node = sidx[r];
            acc = fmaf(fit[r], g_xc[(size_t)(base + node) * C + ch], acc);
        }
        tile[tid] = acc;
    }
    __syncthreads();
    if (tid < C) {
        float s = 0.f;
        #pragma unroll
        for (int k2 = 0; k2 < 8; k2++) s += tile[tid + 128 * k2];
        qd[tid] = s * (1.f / (float)KSEL);
    }
    __syncthreads();
    if (tid < C) {
        float acc = b2[tid];
        #pragma unroll 4
        for (int c = 0; c < C; c++) acc = fmaf(qd[c], W2[c * C + tid], acc);
        out[g * C + tid] = acc;
    }
}

// ---------------- launcher ----------------
extern "C" void kernel_launch(void* const* d_in, const int* in_sizes, int n_in,
                              void* d_out, int out_size) {
    const float* x   = (const float*)d_in[0];
    const float* W1  = (const float*)d_in[1];
    const float* b1  = (const float*)d_in[2];
    const float* Wp  = (const float*)d_in[3];
    const float* bp  = (const float*)d_in[4];
    const float* Wa  = (const float*)d_in[5];
    const float* ba  = (const float*)d_in[6];
    const float* Wl1 = (const float*)d_in[7];
    const float* bl1 = (const float*)d_in[8];
    const float* Wl2 = (const float*)d_in[9];
    const float* Wl3 = (const float*)d_in[10];
    const float* bl3 = (const float*)d_in[11];
    const float* W2  = (const float*)d_in[12];
    const float* b2  = (const float*)d_in[13];
    const int*   ei  = (const int*)d_in[14];   // int32 (JAX x64 disabled)
    int E = in_sizes[14] / 2;
    float* out = (float*)d_out;

    cudaFuncSetAttribute(k_mega, cudaFuncAttributeMaxDynamicSharedMemorySize,
                         SM_BYTES);

    k_gemm_relu<<<N_NODES / 128, 256>>>(x, W1, b1);
    k_prep<<<C, 128>>>(Wp, bp, Wa, ba);
    k_mega<<<BGR, MT, SM_BYTES>>>(ei, E, Wa, Wl1, bl1, Wl2, Wl3, bl3,
                                  W2, b2, out);
}

// round 10
// speedup vs baseline: 2.0759x; 1.1172x over previous
#include <cuda_runtime.h>
#include <cuda_bf16.h>
#include <cstdint>

#define N_NODES 65536
#define C 128
#define BGR 128
#define NPG 512
#define KSEL 256
#define DEG 16
#define E_RAND_PG (NPG * DEG)
#define E_LOC (E_RAND_PG + NPG)
#define MT 1024
#define CHUNK 64
#define PADK 136                  // bf16 row stride (272B: 16B-aligned, conflict-free)

// ---------------- device scratch ----------------
__device__ __align__(16) float g_h[N_NODES * C];
__device__ __align__(16) float g_xc[N_NODES * C];
__device__ __align__(16) float g_v[C];
__device__ __align__(16) __nv_bfloat16 g_wh[C * C];  // W1^T hi [n][k]
__device__ __align__(16) __nv_bfloat16 g_wl[C * C];  // W1^T lo [n][k]
__device__ float g_c;

__device__ __forceinline__ float wsum(float v) {
    #pragma unroll
    for (int o = 16; o > 0; o >>= 1) v += __shfl_xor_sync(0xffffffffu, v, o);
    return v;
}
__device__ __forceinline__ float wmax(float v) {
    #pragma unroll
    for (int o = 16; o > 0; o >>= 1) v = fmaxf(v, __shfl_xor_sync(0xffffffffu, v, o));
    return v;
}
__device__ __forceinline__ float hsum16(float v) {
    #pragma unroll
    for (int o = 8; o > 0; o >>= 1) v += __shfl_xor_sync(0xffffffffu, v, o);
    return v;
}
__device__ __forceinline__ uint32_t smem_u32(const void* p) {
    uint32_t a;
    asm("{ .reg .u64 t; cvta.to.shared.u64 t, %1; cvt.u32.u64 %0, t; }" : "=r"(a) : "l"(p));
    return a;
}
__device__ __forceinline__ void ldsm4(uint32_t* d, uint32_t addr) {
    asm volatile("ldmatrix.sync.aligned.m8n8.x4.shared.b16 {%0,%1,%2,%3}, [%4];"
                 : "=r"(d[0]), "=r"(d[1]), "=r"(d[2]), "=r"(d[3]) : "r"(addr));
}
__device__ __forceinline__ void ldsm2(uint32_t* d, uint32_t addr) {
    asm volatile("ldmatrix.sync.aligned.m8n8.x2.shared.b16 {%0,%1}, [%2];"
                 : "=r"(d[0]), "=r"(d[1]) : "r"(addr));
}
__device__ __forceinline__ void mma16816(float* c, const uint32_t* a, const uint32_t* b) {
    asm volatile("mma.sync.aligned.m16n8k16.row.col.f32.bf16.bf16.f32 "
                 "{%0,%1,%2,%3}, {%4,%5,%6,%7}, {%8,%9}, {%0,%1,%2,%3};"
                 : "+f"(c[0]), "+f"(c[1]), "+f"(c[2]), "+f"(c[3])
                 : "r"(a[0]), "r"(a[1]), "r"(a[2]), "r"(a[3]), "r"(b[0]), "r"(b[1]));
}

// ---------------- W1 -> transposed bf16 hi/lo ----------------
__global__ void k_wconv(const float* __restrict__ W1) {
    int k = blockIdx.x, n = threadIdx.x;
    float w = W1[k * C + n];
    __nv_bfloat16 hi = __float2bfloat16(w);
    g_wh[n * C + k] = hi;
    g_wl[n * C + k] = __float2bfloat16(w - __bfloat162float(hi));
}

// v[k] = sum_j Wp[k,j]*Wa[j];  c = bp.Wa[:128] + ba
__global__ void k_prep(const float* __restrict__ Wp, const float* __restrict__ bp,
                       const float* __restrict__ Wa, const float* __restrict__ ba) {
    int k = blockIdx.x, t = threadIdx.x;
    __shared__ float red[4], red2[4];
    int w = t >> 5, lane = t & 31;
    float s = wsum(Wp[k * C + t] * Wa[t]);
    if (lane == 0) red[w] = s;
    if (k == 0) {
        float q = wsum(bp[t] * Wa[t]);
        if (lane == 0) red2[w] = q;
    }
    __syncthreads();
    if (t == 0) {
        g_v[k] = red[0] + red[1] + red[2] + red[3];
        if (k == 0) g_c = red2[0] + red2[1] + red2[2] + red2[3] + ba[0];
    }
}

// ---------------- h = relu(x @ W1 + b1) via mma.sync bf16x3 ----------------
#define TILE_B 34816
#define SM_GEMM (512 + 4 * TILE_B)

__global__ void __launch_bounds__(256)
k_gemm_mma(const float* __restrict__ X, const float* __restrict__ bias) {
    extern __shared__ char smg[];
    float* bias_s = (float*)smg;
    __nv_bfloat16* Ah = (__nv_bfloat16*)(smg + 512);
    __nv_bfloat16* Al = Ah + C * PADK;
    __nv_bfloat16* Bh = Al + C * PADK;
    __nv_bfloat16* Bl = Bh + C * PADK;

    const int tid = threadIdx.x, wid = tid >> 5, lane = tid & 31;
    const int row0 = blockIdx.x * 128;

    if (tid < C) bias_s[tid] = bias[tid];

    // load+convert A (fp32 -> bf16 hi/lo), copy B tiles
    #pragma unroll
    for (int i = 0; i < 32; i++) {
        int idx = (i * 256 + tid) * 2;
        int r = idx >> 7, k = idx & 127;
        float2 xv = *(const float2*)&X[(size_t)(row0 + r) * C + k];
        __nv_bfloat16 h0 = __float2bfloat16(xv.x);
        __nv_bfloat16 h1 = __float2bfloat16(xv.y);
        __nv_bfloat16 l0 = __float2bfloat16(xv.x - __bfloat162float(h0));
        __nv_bfloat16 l1 = __float2bfloat16(xv.y - __bfloat162float(h1));
        *(__nv_bfloat162*)&Ah[r * PADK + k] = __nv_bfloat162(h0, h1);
        *(__nv_bfloat162*)&Al[r * PADK + k] = __nv_bfloat162(l0, l1);
        *(uint32_t*)&Bh[r * PADK + k] = *(const uint32_t*)&g_wh[r * C + k];
        *(uint32_t*)&Bl[r * PADK + k] = *(const uint32_t*)&g_wl[r * C + k];
    }
    __syncthreads();

    const uint32_t a_hi = smem_u32(Ah);
    const uint32_t b_hi = smem_u32(Bh);

    float c[16][4];
    #pragma unroll
    for (int nt = 0; nt < 16; nt++)
        #pragma unroll
        for (int q = 0; q < 4; q++) c[nt][q] = 0.f;

    const int wr = wid * 16;
    const int arow = wr + (lane & 7) + ((lane >> 3) & 1) * 8;
    const int brow_l = lane & 7;
    const int bk_sel = ((lane >> 3) & 1) * 8;

    #pragma unroll
    for (int k0 = 0; k0 < 8; k0++) {
        int akc = k0 * 16 + (lane >> 4) * 8;
        uint32_t aaddr = a_hi + (uint32_t)(arow * PADK + akc) * 2;
        uint32_t ah[4], al[4];
        ldsm4(ah, aaddr);
        ldsm4(al, aaddr + TILE_B);
        #pragma unroll
        for (int nt = 0; nt < 16; nt++) {
            // non-trans ldmatrix: rows walk n, delivers B(k,n) fragment for
            // col-major B stored as W1^T [n][k]
            uint32_t baddr = b_hi;
            if (lane < 16)
                baddr += (uint32_t)((nt * 8 + brow_l) * PADK + k0 * 16 + bk_sel) * 2;
            uint32_t bh[2], bl[2];
            ldsm2(bh, baddr);
            ldsm2(bl, baddr + TILE_B);
            mma16816(c[nt], ah, bh);
            mma16816(c[nt], ah, bl);
            mma16816(c[nt], al, bh);
        }
    }

    // epilogue: bias + relu
    const int r = lane >> 2, cq = (lane & 3) * 2;
    #pragma unroll
    for (int nt = 0; nt < 16; nt++) {
        int col = nt * 8 + cq;
        float b0 = bias_s[col], b1 = bias_s[col + 1];
        int row = row0 + wr + r;
        *(float2*)&g_h[(size_t)row * C + col] =
            make_float2(fmaxf(c[nt][0] + b0, 0.f), fmaxf(c[nt][1] + b1, 0.f));
        *(float2*)&g_h[(size_t)(row + 8) * C + col] =
            make_float2(fmaxf(c[nt][2] + b0, 0.f), fmaxf(c[nt][3] + b1, 0.f));
    }
}

// ---------------- mega kernel: one block per graph, 1024 threads ----------------
#define SM_BYTES (131072 + 2048*8 + 2056 + 2048 + 34816 + 17408)

__device__ __forceinline__ int scan512(int v, int tid, int* scratch) {
    int lane = tid & 31, w = tid >> 5;
    #pragma unroll
    for (int o = 1; o < 32; o <<= 1) {
        int u = __shfl_up_sync(0xffffffffu, v, o);
        if (lane >= o) v += u;
    }
    if (tid < NPG && lane == 31) scratch[w] = v;
    __syncthreads();
    if (tid < 16) {
        int s = scratch[tid];
        #pragma unroll
        for (int o = 1; o < 16; o <<= 1) {
            int u = __shfl_up_sync(0xffffu, s, o);
            if (tid >= o) s += u;
        }
        scratch[tid] = s;
    }
    __syncthreads();
    if (w > 0 && tid < NPG) v += scratch[w - 1];
    return v;
}

extern "C" __global__ void __launch_bounds__(MT, 1)
k_mega(const int* __restrict__ ei, int E,
       const float* __restrict__ Wa,
       const float* __restrict__ Wl1, const float* __restrict__ bl1,
       const float* __restrict__ Wl2,
       const float* __restrict__ Wl3, const float* __restrict__ bl3,
       const float* __restrict__ W2, const float* __restrict__ b2,
       float* __restrict__ out) {
    extern __shared__ char sm[];
    float* tile = (float*)sm;
    float* hdot = tile + NPG * CHUNK;
    float* qd   = hdot + NPG;
    float* smax = qd + NPG;                           // reused as fw[]
    float* sinv = smax + NPG;
    float* f1   = sinv + NPG;
    float* f2   = f1 + NPG;
    float* f3   = f2 + NPG;
    float* fit  = f3 + NPG;
    int*   off  = (int*)(fit + NPG);
    int*   cur  = off + NPG + 2;
    float* alpha = (float*)(cur + NPG);
    unsigned short* csr = (unsigned short*)(alpha + E_LOC);

    const int g = blockIdx.x;
    const int base = g * NPG;
    const int tid = threadIdx.x;
    const int wid = tid >> 5;
    const int lane = tid & 31;
    const int hw = tid >> 4;
    const int l16 = tid & 15;
    const int ch4 = l16 * 4;

    // ---- local CSR build ----
    if (tid < NPG) cur[tid] = 1;
    __syncthreads();
    for (int e = tid; e < E_RAND_PG; e += MT) {
        int dst = ei[(size_t)E + base * DEG + e] - base;
        atomicAdd(&cur[dst], 1);
    }
    __syncthreads();
    {
        int v = (tid < NPG) ? cur[tid] : 0;
        v = scan512(v, tid, (int*)hdot);
        if (tid < NPG) off[tid + 1] = v;
        if (tid == 0) off[0] = 0;
    }
    __syncthreads();
    if (tid < NPG) cur[tid] = 0;
    __syncthreads();
    for (int e = tid; e < E_RAND_PG; e += MT) {
        int dst = ei[(size_t)E + base * DEG + e] - base;
        int src = ei[base * DEG + e] - base;
        int p = off[dst] + atomicAdd(&cur[dst], 1);
        csr[p] = (unsigned short)src;
    }
    __syncthreads();
    if (tid < NPG) {
        int p = off[tid] + atomicAdd(&cur[tid], 1);
        csr[p] = (unsigned short)tid;
    }
    __syncthreads();

    const float gc = g_c;

    // ==== phase A ====
    #pragma unroll
    for (int c = 0; c < 2; c++) {
        {
            const float* wa2 = Wa + C + c * CHUNK;
            float w0 = wa2[ch4], w1 = wa2[ch4 + 1], w2 = wa2[ch4 + 2], w3 = wa2[ch4 + 3];
            #pragma unroll
            for (int r = 0; r < 8; r++) {
                int row = hw + r * 64;
                float4 hv = *(const float4*)(g_h + (size_t)(base + row) * C + c * CHUNK + ch4);
                *(float4*)(tile + row * CHUNK + ch4) = hv;
                float p = hsum16(hv.x * w0 + hv.y * w1 + hv.z * w2 + hv.w * w3);
                if (l16 == 0) { if (c == 0) hdot[row] = p; else hdot[row] += p; }
            }
        }
        __syncthreads();
        {
            float4 vv = *(const float4*)(g_v + c * CHUNK + ch4);
            for (int n = hw; n < NPG; n += 64) {
                int s0 = off[n], s1 = off[n + 1];
                float4 m = make_float4(0.f, 0.f, 0.f, 0.f);
                int e = s0;
                for (; e + 4 <= s1; e += 4) {
                    int i0 = csr[e], i1 = csr[e + 1], i2 = csr[e + 2], i3 = csr[e + 3];
                    float4 a0 = *(const float4*)(tile + i0 * CHUNK + ch4);
                    float4 a1 = *(const float4*)(tile + i1 * CHUNK + ch4);
                    float4 a2 = *(const float4*)(tile + i2 * CHUNK + ch4);
                    float4 a3 = *(const float4*)(tile + i3 * CHUNK + ch4);
                    m.x = fmaxf(fmaxf(fmaxf(m.x, a0.x), fmaxf(a1.x, a2.x)), a3.x);
                    m.y = fmaxf(fmaxf(fmaxf(m.y, a0.y), fmaxf(a1.y, a2.y)), a3.y);
                    m.z = fmaxf(fmaxf(fmaxf(m.z, a0.z), fmaxf(a1.z, a2.z)), a3.z);
                    m.w = fmaxf(fmaxf(fmaxf(m.w, a0.w), fmaxf(a1.w, a2.w)), a3.w);
                }
                for (; e < s1; e++) {
                    float4 a0 = *(const float4*)(tile + csr[e] * CHUNK + ch4);
                    m.x = fmaxf(m.x, a0.x); m.y = fmaxf(m.y, a0.y);
                    m.z = fmaxf(m.z, a0.z); m.w = fmaxf(m.w, a0.w);
                }
                float p = hsum16(m.x * vv.x + m.y * vv.y + m.z * vv.z + m.w * vv.w);
                if (l16 == 0) { if (c == 0) qd[n] = p; else qd[n] += p; }
            }
        }
        __syncthreads();
    }

    // ==== phase B ====
    for (int n = wid; n < NPG; n += 32) {
        int s0 = off[n], s1 = off[n + 1];
        float mh = -3.0e38f;
        for (int e = s0 + lane; e < s1; e += 32) mh = fmaxf(mh, hdot[csr[e]]);
        mh = wmax(mh);
        float q = qd[n] + gc;
        float sm2 = q + mh;
        sm2 = sm2 > 0.f ? sm2 : 0.2f * sm2;
        float ss = 0.f;
        for (int e = s0 + lane; e < s1; e += 32) {
            float sc = q + hdot[csr[e]];
            sc = sc > 0.f ? sc : 0.2f * sc;
            float es = __expf(sc - sm2);
            alpha[e] = es;
            ss += es;
        }
        ss = wsum(ss);
        if (lane == 0) sinv[n] = 1.f / ss;
    }
    __syncthreads();

    // ==== phase C ====
    #pragma unroll
    for (int cc = 0; cc < 2; cc++) {
        int c = 1 - cc;
        if (cc == 1) {
            #pragma unroll
            for (int r = 0; r < 8; r++) {
                int row = hw + r * 64;
                float4 hv = *(const float4*)(g_h + (size_t)(base + row) * C + c * CHUNK + ch4);
                *(float4*)(tile + row * CHUNK + ch4) = hv;
            }
            __syncthreads();
        }
        float w10 = Wl1[c * CHUNK + ch4], w11 = Wl1[c * CHUNK + ch4 + 1],
              w12 = Wl1[c * CHUNK + ch4 + 2], w13 = Wl1[c * CHUNK + ch4 + 3];
        float w20 = Wl2[c * CHUNK + ch4], w21 = Wl2[c * CHUNK + ch4 + 1],
              w22 = Wl2[c * CHUNK + ch4 + 2], w23 = Wl2[c * CHUNK + ch4 + 3];
        float w30 = Wl3[c * CHUNK + ch4], w31 = Wl3[c * CHUNK + ch4 + 1],
              w32 = Wl3[c * CHUNK + ch4 + 2], w33 = Wl3[c * CHUNK + ch4 + 3];
        for (int n = hw; n < NPG; n += 64) {
            int s0 = off[n], s1 = off[n + 1];
            float iv = sinv[n];
            float ax = 0.f, ay = 0.f, az = 0.f, aw = 0.f;
            int e = s0;
            for (; e + 4 <= s1; e += 4) {
                int i0 = csr[e], i1 = csr[e + 1], i2 = csr[e + 2], i3 = csr[e + 3];
                float e0 = alpha[e], e1 = alpha[e + 1], e2 = alpha[e + 2], e3 = alpha[e + 3];
                float4 a0 = *(const float4*)(tile + i0 * CHUNK + ch4);
                float4 a1 = *(const float4*)(tile + i1 * CHUNK + ch4);
                float4 a2 = *(const float4*)(tile + i2 * CHUNK + ch4);
                float4 a3 = *(const float4*)(tile + i3 * CHUNK + ch4);
                ax = fmaf(e0, a0.x, fmaf(e1, a1.x, fmaf(e2, a2.x, fmaf(e3, a3.x, ax))));
                ay = fmaf(e0, a0.y, fmaf(e1, a1.y, fmaf(e2, a2.y, fmaf(e3, a3.y, ay))));
                az = fmaf(e0, a0.z, fmaf(e1, a1.z, fmaf(e2, a2.z, fmaf(e3, a3.z, az))));
                aw = fmaf(e0, a0.w, fmaf(e1, a1.w, fmaf(e2, a2.w, fmaf(e3, a3.w, aw))));
            }
            for (; e < s1; e++) {
                float e0 = alpha[e];
                float4 a0 = *(const float4*)(tile + csr[e] * CHUNK + ch4);
                ax = fmaf(e0, a0.x, ax); ay = fmaf(e0, a0.y, ay);
                az = fmaf(e0, a0.z, az); aw = fmaf(e0, a0.w, aw);
            }
            ax *= iv; ay *= iv; az *= iv; aw *= iv;
            *(float4*)(g_xc + (size_t)(base + n) * C + c * CHUNK + ch4) =
                make_float4(ax, ay, az, aw);
            float d1 = hsum16(ax * w10 + ay * w11 + az * w12 + aw * w13);
            float d2 = hsum16(ax * w20 + ay * w21 + az * w22 + aw * w23);
            float d3 = hsum16(ax * w30 + ay * w31 + az * w32 + aw * w33);
            if (l16 == 0) {
                if (cc == 0) { f1[n] = d1; f2[n] = d2; f3[n] = d3; }
                else { f1[n] += d1; f2[n] += d2; f3[n] += d3; }
            }
        }
        __syncthreads();
    }

    // ==== phase D ====
    if (tid < NPG) {
        float deg = (float)(off[tid + 1] - off[tid]);
        f1[tid] = f1[tid] + bl1[0];
        f3[tid] = f3[tid] + bl3[0] - deg * f2[tid];
    }
    __syncthreads();
    for (int n = wid; n < NPG; n += 32) {
        int s0 = off[n], s1 = off[n + 1];
        float s = 0.f;
        for (int e = s0 + lane; e < s1; e += 32) s += f1[csr[e]];
        s = wsum(s);
        if (lane == 0) fit[n] = 1.f / (1.f + __expf(-(f3[n] + s)));
    }
    __syncthreads();

    // ==== phase E: rank-based top-K (desc, tie -> smaller index) ====
    int* sidx = cur;
    float* fw = smax;
    int selv = 0;
    float fi = 0.f;
    if (tid < NPG) {
        fi = fit[tid];
        int r = 0;
        for (int j = 0; j < NPG; j++) {
            float fj = fit[j];
            r += (fj > fi || (fj == fi && j < tid)) ? 1 : 0;
        }
        selv = (r < KSEL) ? 1 : 0;
    }
    int pos = scan512(selv, tid, (int*)hdot);
    __syncthreads();
    if (tid < NPG && selv) { sidx[pos - 1] = tid; fw[pos - 1] = fi; }
    __syncthreads();

    // ==== phase F ====
    {
        int ch = tid & 127, grp = tid >> 7;
        float acc = 0.f;
        for (int r = grp * 32; r < grp * 32 + 32; r++) {
            int node = sidx[r];
            acc = fmaf(fw[r], g_xc[(size_t)(base + node) * C + ch], acc);
        }
        tile[tid] = acc;
    }
    __syncthreads();
    if (tid < C) {
        float s = 0.f;
        #pragma unroll
        for (int k2 = 0; k2 < 8; k2++) s += tile[tid + 128 * k2];
        qd[tid] = s * (1.f / (float)KSEL);
    }
    __syncthreads();
    if (tid < C) {
        float acc = b2[tid];
        #pragma unroll 4
        for (int c = 0; c < C; c++) acc = fmaf(qd[c], W2[c * C + tid], acc);
        out[g * C + tid] = acc;
    }
}

// ---------------- launcher ----------------
extern "C" void kernel_launch(void* const* d_in, const int* in_sizes, int n_in,
                              void* d_out, int out_size) {
    const float* x   = (const float*)d_in[0];
    const float* W1  = (const float*)d_in[1];
    const float* b1  = (const float*)d_in[2];
    const float* Wp  = (const float*)d_in[3];
    const float* bp  = (const float*)d_in[4];
    const float* Wa  = (const float*)d_in[5];
    const float* ba  = (const float*)d_in[6];
    const float* Wl1 = (const float*)d_in[7];
    const float* bl1 = (const float*)d_in[8];
    const float* Wl2 = (const float*)d_in[9];
    const float* Wl3 = (const float*)d_in[10];
    const float* bl3 = (const float*)d_in[11];
    const float* W2  = (const float*)d_in[12];
    const float* b2  = (const float*)d_in[13];
    const int*   ei  = (const int*)d_in[14];
    int E = in_sizes[14] / 2;
    float* out = (float*)d_out;

    cudaFuncSetAttribute(k_gemm_mma, cudaFuncAttributeMaxDynamicSharedMemorySize, SM_GEMM);
    cudaFuncSetAttribute(k_mega, cudaFuncAttributeMaxDynamicSharedMemorySize, SM_BYTES);

    k_wconv<<<C, C>>>(W1);
    k_prep<<<C, 128>>>(Wp, bp, Wa, ba);
    k_gemm_mma<<<N_NODES / 128, 256, SM_GEMM>>>(x, b1);
    k_mega<<<BGR, MT, SM_BYTES>>>(ei, E, Wa, Wl1, bl1, Wl2, Wl3, bl3,
                                  W2, b2, out);
}